// round 16
// baseline (speedup 1.0000x reference)
#include <cuda_runtime.h>
#include <cuda_fp16.h>
#include <math.h>
#include <stdint.h>

#define NPTS     131072
#define HDIM     256
#define PTS      16              // points per CTA
#define NTH      256             // 8 warps, 1x8 grid (M=64 all, N=32 per warp)
#define NBLK     (NPTS / PTS)    // 8192
#define AP       264             // A smem pitch (halfs): 528B, conflict-free ldmatrix
#define GAMMA_F  (5.0f / 3.0f)

// Fragment-ready W: [t = L*16+ks][g=0..15][lane=0..31] -> uint4 (16B)
// +1 pad t-slot so the ks-loop prefetch is branchless.
__device__ __align__(16) uint4 g_Wf[33 * 16 * 32];
__device__ float g_partial[NBLK];
__device__ unsigned int g_count = 0;

struct __align__(16) Smem {
    __half A[64 * AP];              // 33792 B   rows: v*16 + p
    float bias_s[HDIM];
    float W1s[3][HDIM];
    float W4Ts[6][HDIM];
    float OUT[4][PTS][6];
    float coords[PTS][3];
    float b4s[6];
    float warp_s[8];
    int   done;
};

// ---------------- asm helpers (baseline sm_80+ PTX only) ----------------
__device__ __forceinline__ uint32_t smem_u32(const void* p) {
    uint32_t a;
    asm("{ .reg .u64 t; cvta.to.shared.u64 t, %1; cvt.u32.u64 %0, t; }" : "=r"(a) : "l"(p));
    return a;
}
#define LDSM4(r0, r1, r2, r3, addr) \
    asm volatile("ldmatrix.sync.aligned.m8n8.x4.shared.b16 {%0,%1,%2,%3}, [%4];" \
                 : "=r"(r0), "=r"(r1), "=r"(r2), "=r"(r3) : "r"(addr))

#define MMAF16(d, a, b0, b1) \
    asm volatile("mma.sync.aligned.m16n8k16.row.col.f32.f16.f16.f32 " \
                 "{%0,%1,%2,%3}, {%4,%5,%6,%7}, {%8,%9}, {%0,%1,%2,%3};" \
                 : "+f"((d)[0]), "+f"((d)[1]), "+f"((d)[2]), "+f"((d)[3]) \
                 : "r"((a)[0]), "r"((a)[1]), "r"((a)[2]), "r"((a)[3]), \
                   "r"(b0), "r"(b1))

// ---------------- prep: W2/W3 fp32 [k][n] -> fragment-ready fp16 ----------------
__global__ void prep_kernel(const float* __restrict__ W2, const float* __restrict__ W3) {
    int id = blockIdx.x * blockDim.x + threadIdx.x;      // 0..16383
    int l  = id & 31;
    int g  = (id >> 5) & 15;
    int t  = id >> 9;                                    // 0..31
    const float* W = (t >= 16) ? W3 : W2;
    int ks = t & 15;
    int n0 = g * 16 + (l >> 2);
    int n1 = n0 + 8;
    int kb = ks * 16 + 2 * (l & 3);

    __half2 x = __floats2half2_rn(W[kb * HDIM + n0],       W[(kb + 1) * HDIM + n0]);
    __half2 y = __floats2half2_rn(W[(kb + 8) * HDIM + n0], W[(kb + 9) * HDIM + n0]);
    __half2 z = __floats2half2_rn(W[kb * HDIM + n1],       W[(kb + 1) * HDIM + n1]);
    __half2 w = __floats2half2_rn(W[(kb + 8) * HDIM + n1], W[(kb + 9) * HDIM + n1]);

    uint4 v;
    v.x = *(uint32_t*)&x; v.y = *(uint32_t*)&y;
    v.z = *(uint32_t*)&z; v.w = *(uint32_t*)&w;
    g_Wf[((t * 16) + g) * 32 + l] = v;
    if (id < 16 * 32) {  // zero the pad slot (t=32)
        uint4 zv = {0u, 0u, 0u, 0u};
        g_Wf[(32 * 16) * 32 + id] = zv;
    }
}

// ---------------- main fused kernel ----------------
__global__ void __launch_bounds__(NTH, 2)
mhd_kernel(const float* __restrict__ coords,
           const float* __restrict__ W1, const float* __restrict__ b1,
           const float* __restrict__ b2, const float* __restrict__ b3,
           const float* __restrict__ W4, const float* __restrict__ b4,
           const float* __restrict__ wts, float* __restrict__ out) {
    extern __shared__ char raw[];
    Smem* s = (Smem*)raw;
    const int tid = threadIdx.x, wid = tid >> 5, lane = tid & 31;
    const int gid = lane >> 2, tig = lane & 3;     // fragment coords

    const uint32_t a_b = smem_u32(s->A);

    // ---- stage constants ----
    for (int i = tid; i < 3 * HDIM; i += NTH) ((float*)s->W1s)[i] = W1[i];
    for (int i = tid; i < 6 * HDIM; i += NTH) {
        int k = i / 6, j = i % 6;
        s->W4Ts[j][k] = W4[i];
    }
    if (tid < PTS * 3) ((float*)s->coords)[tid] = coords[blockIdx.x * PTS * 3 + tid];
    if (tid < 6) s->b4s[tid] = b4[tid];
    __syncthreads();

    // ---- layer 1: 3 -> 256, seed A rows v*16+p ----
    #pragma unroll
    for (int i = 0; i < 8; i++) {
        int idx = tid + i * NTH;                 // 0..2047
        int p = idx >> 7, n = (idx & 127) * 2;
        float w00 = s->W1s[0][n], w01 = s->W1s[0][n + 1];
        float w10 = s->W1s[1][n], w11 = s->W1s[1][n + 1];
        float w20 = s->W1s[2][n], w21 = s->W1s[2][n + 1];
        float c0 = s->coords[p][0], c1 = s->coords[p][1], c2 = s->coords[p][2];
        float z0 = fmaf(c2, w20, fmaf(c1, w10, fmaf(c0, w00, b1[n])));
        float z1 = fmaf(c2, w21, fmaf(c1, w11, fmaf(c0, w01, b1[n + 1])));
        float h0 = tanhf(z0), h1 = tanhf(z1);
        float sd0 = 1.f - h0 * h0, sd1 = 1.f - h1 * h1;
        *(__half2*)&s->A[p * AP + n]        = __floats2half2_rn(h0, h1);
        *(__half2*)&s->A[(16 + p) * AP + n] = __floats2half2_rn(sd0 * w00, sd1 * w01);
        *(__half2*)&s->A[(32 + p) * AP + n] = __floats2half2_rn(sd0 * w10, sd1 * w11);
        *(__half2*)&s->A[(48 + p) * AP + n] = __floats2half2_rn(sd0 * w20, sd1 * w21);
    }
    __syncthreads();

    // per-lane A ldmatrix address components
    const uint32_t a_rowsel = (uint32_t)(lane & 15);
    const uint32_t a_colsel = (uint32_t)((lane >> 4) << 3);
    const uint32_t a_base = a_b + (a_rowsel * AP + a_colsel) * 2u;

    // B fragment pointer for this warp: groups wid*2, wid*2+1
    const uint4* wf = &g_Wf[(size_t)(wid * 2) * 32 + lane];

    // ---- layers 2 & 3: LDG-fragment fp16 HMMA, no smem for W ----
    const float* biases[2] = {b2, b3};
    uint4 bc0 = wf[0], bc1 = wf[32];               // t = 0 prefetched

    #pragma unroll
    for (int L = 0; L < 2; L++) {
        s->bias_s[tid] = biases[L][tid];

        float acc[4][4][4];
        #pragma unroll
        for (int mt = 0; mt < 4; mt++)
            #pragma unroll
            for (int nt = 0; nt < 4; nt++)
                #pragma unroll
                for (int e = 0; e < 4; e++) acc[mt][nt][e] = 0.f;

        #pragma unroll
        for (int ks = 0; ks < 16; ks++) {
            const int t = L * 16 + ks;
            // branchless prefetch of next-t fragments (pad slot at t=32)
            uint4 bn0 = wf[(size_t)(t + 1) * 16 * 32];
            uint4 bn1 = wf[(size_t)(t + 1) * 16 * 32 + 32];

            uint32_t a[4][4];
            #pragma unroll
            for (int mt = 0; mt < 4; mt++) {
                uint32_t off = (uint32_t)(mt * 16) * (AP * 2u)
                             + (uint32_t)(ks * 16) * 2u;
                LDSM4(a[mt][0], a[mt][1], a[mt][2], a[mt][3], a_base + off);
            }
            #pragma unroll
            for (int mt = 0; mt < 4; mt++) {
                MMAF16(acc[mt][0], a[mt], bc0.x, bc0.y);
                MMAF16(acc[mt][1], a[mt], bc0.z, bc0.w);
                MMAF16(acc[mt][2], a[mt], bc1.x, bc1.y);
                MMAF16(acc[mt][3], a[mt], bc1.z, bc1.w);
            }
            bc0 = bn0; bc1 = bn1;
        }
        __syncthreads();   // all A (old) reads complete

        // ---- epilogue: sd stays in-thread (acc[0] and acc[mt] share (p,n) map) ----
        #pragma unroll
        for (int nt = 0; nt < 4; nt++) {
            int nb = wid * 32 + nt * 8 + 2 * tig;
            float bs0 = s->bias_s[nb], bs1 = s->bias_s[nb + 1];
            #pragma unroll
            for (int eh = 0; eh < 2; eh++) {
                int p = gid + eh * 8;
                float h0 = tanhf(acc[0][nt][eh * 2]     + bs0);
                float h1 = tanhf(acc[0][nt][eh * 2 + 1] + bs1);
                float sd0 = 1.f - h0 * h0, sd1 = 1.f - h1 * h1;
                *(__half2*)&s->A[p * AP + nb] = __floats2half2_rn(h0, h1);
                #pragma unroll
                for (int mt = 1; mt < 4; mt++) {
                    *(__half2*)&s->A[(mt * 16 + p) * AP + nb] =
                        __floats2half2_rn(acc[mt][nt][eh * 2] * sd0,
                                          acc[mt][nt][eh * 2 + 1] * sd1);
                }
            }
        }
        __syncthreads();   // new A visible before next layer / layer 4
    }

    // ---- layer 4: 256 -> 6, k-split over 4 threads per row, vector LDS ----
    {
        int row = tid >> 2;                        // 0..63 = v*16+p
        int ks = tid & 3;
        float acc4[6] = {0.f, 0.f, 0.f, 0.f, 0.f, 0.f};
        const uint4* arow = (const uint4*)&s->A[row * AP + ks * 64];
        #pragma unroll
        for (int v8 = 0; v8 < 8; v8++) {
            uint4 av = arow[v8];
            const __half2* hp = (const __half2*)&av;
            #pragma unroll
            for (int q = 0; q < 4; q++) {
                float2 f2 = __half22float2(hp[q]);
                int k = ks * 64 + v8 * 8 + q * 2;
                #pragma unroll
                for (int j = 0; j < 6; j++)
                    acc4[j] = fmaf(f2.y, s->W4Ts[j][k + 1],
                              fmaf(f2.x, s->W4Ts[j][k], acc4[j]));
            }
        }
        #pragma unroll
        for (int j = 0; j < 6; j++) {
            acc4[j] += __shfl_down_sync(0xffffffffu, acc4[j], 2, 4);
            acc4[j] += __shfl_down_sync(0xffffffffu, acc4[j], 1, 4);
        }
        if (ks == 0) {
            int v = row >> 4, p = row & 15;
            #pragma unroll
            for (int j = 0; j < 6; j++)
                s->OUT[v][p][j] = acc4[j] + ((v == 0) ? s->b4s[j] : 0.f);
        }
    }
    __syncthreads();

    // ---- residuals + reduction over the CTA's 16 points ----
    if (tid < PTS) {
        const int m = tid;
        const float* P  = s->OUT[0][m];
        const float* Jx = s->OUT[1][m];
        const float* Jy = s->OUT[2][m];
        const float* Jt = s->OUT[3][m];
        const float rho = P[0], vx = P[1], vy = P[2], Bx = P[3], By = P[4], Pp = P[5];
        const float ig = 1.f / (GAMMA_F - 1.f);

        const float dt_rho = Jt[0], dt_Bx = Jt[3], dt_By = Jt[4];
        const float dt_rhovx = dt_rho * vx + rho * Jt[1];
        const float dt_rhovy = dt_rho * vy + rho * Jt[2];

        #define DE(Jc) ((Jc)[5] * ig + 0.5f * (Jc)[0] * (vx * vx + vy * vy) \
                        + rho * (vx * (Jc)[1] + vy * (Jc)[2]) + Bx * (Jc)[3] + By * (Jc)[4])
        #define DG(Jc) ((Jc)[1] * By + vx * (Jc)[4] - (Jc)[2] * Bx - vy * (Jc)[3])
        #define DD(Jc) ((Jc)[3] * vx + Bx * (Jc)[1] + (Jc)[4] * vy + By * (Jc)[2])

        const float dE_dx = DE(Jx), dE_dy = DE(Jy), dE_dt = DE(Jt);
        const float div_v = Jx[1] + Jy[2];
        const float div_B = Jx[3] + Jy[4];
        const float continuity = dt_rho + rho * div_v;
        const float dPm_dx = Jx[5] + Bx * Jx[3] + By * Jx[4];
        const float dPm_dy = Jy[5] + Bx * Jy[3] + By * Jy[4];
        const float momentum_x = dt_rhovx + dPm_dx - (Bx * Jx[3] + By * Jy[3]);
        const float momentum_y = dt_rhovy + dPm_dy - (Bx * Jx[4] + By * Jy[4]);
        const float induction_x = dt_Bx + DG(Jy);
        const float induction_y = dt_By - DG(Jx);
        const float Ee = Pp * ig + 0.5f * rho * (vx * vx + vy * vy) + 0.5f * (Bx * Bx + By * By);
        const float S  = Ee + Pp + 0.5f * (Bx * Bx + By * By);
        const float dS_dx = dE_dx + Jx[5] + Bx * Jx[3] + By * Jx[4];
        const float dS_dy = dE_dy + Jy[5] + Bx * Jy[3] + By * Jy[4];
        const float D = Bx * vx + By * vy;
        const float dFx_dx = dS_dx * vx + S * Jx[1] - DD(Jx) * Bx - D * Jx[3];
        const float dFy_dy = dS_dy * vy + S * Jy[2] - DD(Jy) * By - D * Jy[4];
        const float energy = dE_dt + dFx_dx + dFy_dy;

        float Sm = wts[0] * continuity * continuity
                 + wts[1] * momentum_x * momentum_x
                 + wts[2] * momentum_y * momentum_y
                 + wts[3] * induction_x * induction_x
                 + wts[4] * induction_y * induction_y
                 + wts[5] * energy * energy
                 + wts[6] * div_B * div_B;

        #pragma unroll
        for (int off = 8; off; off >>= 1)
            Sm += __shfl_down_sync(0x0000ffffu, Sm, off, 16);
        if (m == 0) g_partial[blockIdx.x] = Sm;
    }

    // ---- last-block final reduction (deterministic) ----
    if (tid == 0) {
        __threadfence();
        unsigned int ticket = atomicAdd(&g_count, 1u);
        s->done = (ticket == NBLK - 1) ? 1 : 0;
    }
    __syncthreads();
    if (s->done) {
        __threadfence();
        float sum = 0.f;
        for (int i = tid; i < NBLK; i += NTH) sum += g_partial[i];
        #pragma unroll
        for (int off = 16; off; off >>= 1) sum += __shfl_down_sync(0xffffffffu, sum, off);
        if (lane == 0) s->warp_s[wid] = sum;
        __syncthreads();
        if (tid < 32) {
            sum = (lane < 8) ? s->warp_s[lane] : 0.f;
            #pragma unroll
            for (int off = 4; off; off >>= 1) sum += __shfl_down_sync(0xffffffffu, sum, off);
            if (lane == 0) {
                out[0] = sum / (float)NPTS;
                g_count = 0;
            }
        }
    }
}

extern "C" void kernel_launch(void* const* d_in, const int* in_sizes, int n_in,
                              void* d_out, int out_size) {
    const float* coords = (const float*)d_in[0];
    const float* W1     = (const float*)d_in[1];
    const float* b1     = (const float*)d_in[2];
    const float* W2     = (const float*)d_in[3];
    const float* b2     = (const float*)d_in[4];
    const float* W3     = (const float*)d_in[5];
    const float* b3     = (const float*)d_in[6];
    const float* W4     = (const float*)d_in[7];
    const float* b4     = (const float*)d_in[8];
    const float* wts    = (const float*)d_in[9];

    prep_kernel<<<64, 256>>>(W2, W3);

    const size_t smem_bytes = sizeof(Smem);
    cudaFuncSetAttribute(mhd_kernel, cudaFuncAttributeMaxDynamicSharedMemorySize,
                         (int)smem_bytes);
    mhd_kernel<<<NBLK, NTH, smem_bytes>>>(coords, W1, b1, b2, b3, W4, b4, wts,
                                          (float*)d_out);
}